// round 4
// baseline (speedup 1.0000x reference)
#include <cuda_runtime.h>
#include <cstdint>

// Problem constants
constexpr int B  = 8;
constexpr int C  = 19;
constexpr int H  = 320;
constexpr int W  = 2048;
constexpr int HH_OFF = 10;
constexpr int HH_N  = 10;
constexpr int WW   = 128;
constexpr int P    = HH_N * WW;      // 1280
constexpr long long NE = (long long)B * P * P;

constexpr int WCHUNK = 256;
constexpr int NWCH   = W / WCHUNK;   // 8
constexpr int RWARPS = 8;            // rows (=warps) per attn block
constexpr int CH     = P / 4 / 32;   // float4 chunks per lane = 10

__device__ int g_lab[B * P];

// ---------------------------------------------------------------------------
// K1 (fused pool + argmax): unchanged from R3 (at ~85% of practical HBM ceiling).
// ---------------------------------------------------------------------------
__global__ __launch_bounds__(256) void pool_argmax_kernel(const float* __restrict__ label)
{
    const int wc = blockIdx.x;
    const int hh = blockIdx.y;
    const int b  = blockIdx.z;
    const int t  = threadIdx.x;
    const int f  = t & 63;
    const int cg = t >> 6;

    __shared__ float ssum[C][17];

    const int h0 = (HH_OFF + hh) * 16;
    const int row_f4 = W / 4;

#pragma unroll
    for (int c4 = 0; c4 < 5; c4++) {
        const int c = c4 * 4 + cg;
        float acc = 0.f;
        if (c < C) {
            const float4* p = reinterpret_cast<const float4*>(
                label + (((size_t)b * C + c) * H + h0) * W + wc * WCHUNK) + f;
#pragma unroll
            for (int r = 0; r < 16; r++) {
                float4 v = __ldcs(p + (size_t)r * row_f4);
                acc += (v.x + v.y) + (v.z + v.w);
            }
        }
        acc += __shfl_xor_sync(0xffffffffu, acc, 1);
        acc += __shfl_xor_sync(0xffffffffu, acc, 2);
        if (c < C && (t & 3) == 0) ssum[c][f >> 2] = acc;
    }
    __syncthreads();

    if (t < 16) {
        float best = ssum[0][t];
        int bi = 0;
#pragma unroll
        for (int c = 1; c < C; c++) {
            float v = ssum[c][t];
            if (v > best) { best = v; bi = c; }
        }
        g_lab[(b * HH_N + hh) * WW + wc * 16 + t] = bi;
    }
}

// ---------------------------------------------------------------------------
// K2 (attn): ONE WARP PER ROW. 256 threads = 8 warps = 8 rows per block.
// Lane l handles float4 chunks l, l+32, ..., l+288 (40 floats). Softmax sum
// is a warp-local shfl reduction -> no __syncthreads in the hot path.
// ev stored immediately; ex kept in regs for the attention_map store.
// Softmax without max-shift: post-edit values are N(0,1)-bounded (|v|<~7),
// exp safe in f32; softmax is shift-invariant.
// ---------------------------------------------------------------------------
__global__ __launch_bounds__(256) void attn_kernel(const float* __restrict__ energy,
                                                   float* __restrict__ out)
{
    const int b   = blockIdx.y;
    const int i0  = blockIdx.x * RWARPS;
    const int t   = threadIdx.x;
    const int wid = t >> 5;
    const int lid = t & 31;

    __shared__ int lab_s[P];

    // 256 threads x int4 covers 1024; remaining 256 ints by first 64 threads
    reinterpret_cast<int4*>(lab_s)[t] =
        reinterpret_cast<const int4*>(g_lab + b * P)[t];
    if (t < 64)
        reinterpret_cast<int4*>(lab_s)[256 + t] =
            reinterpret_cast<const int4*>(g_lab + b * P)[256 + t];
    __syncthreads();

    const int i  = i0 + wid;
    const int li = lab_s[i];

    const float4* erow = reinterpret_cast<const float4*>(
        energy + ((size_t)b * P + i) * P);
    float4* eout = reinterpret_cast<float4*>(out + ((size_t)b * P + i) * P);
    float4* aout = reinterpret_cast<float4*>(out + NE + ((size_t)b * P + i) * P);
    const int4* lab4 = reinterpret_cast<const int4*>(lab_s);

    float4 ex[CH];
    float s = 0.f;

#pragma unroll
    for (int k = 0; k < CH; k++) {
        const int j = lid + k * 32;
        float4 en = __ldcs(erow + j);
        int4  lj = lab4[j];

        float4 ev;
        ev.x = (lj.x == li) ? (en.x < 0.f ? 0.5f : en.x) : (en.x > 0.f ? -0.5f : en.x);
        ev.y = (lj.y == li) ? (en.y < 0.f ? 0.5f : en.y) : (en.y > 0.f ? -0.5f : en.y);
        ev.z = (lj.z == li) ? (en.z < 0.f ? 0.5f : en.z) : (en.z > 0.f ? -0.5f : en.z);
        ev.w = (lj.w == li) ? (en.w < 0.f ? 0.5f : en.w) : (en.w > 0.f ? -0.5f : en.w);

        __stcs(eout + j, ev);

        ex[k].x = __expf(ev.x);
        ex[k].y = __expf(ev.y);
        ex[k].z = __expf(ev.z);
        ex[k].w = __expf(ev.w);
        s += (ex[k].x + ex[k].y) + (ex[k].z + ex[k].w);
    }

#pragma unroll
    for (int o = 16; o > 0; o >>= 1) s += __shfl_xor_sync(0xffffffffu, s, o);
    const float inv = 1.f / s;

#pragma unroll
    for (int k = 0; k < CH; k++) {
        const int j = lid + k * 32;
        float4 am;
        am.x = ex[k].x * inv;
        am.y = ex[k].y * inv;
        am.z = ex[k].z * inv;
        am.w = ex[k].w * inv;
        __stcs(aout + j, am);
    }
}

extern "C" void kernel_launch(void* const* d_in, const int* in_sizes, int n_in,
                              void* d_out, int out_size)
{
    const float* label  = (const float*)d_in[0];  // [8,19,320,2048] f32
    const float* energy = (const float*)d_in[1];  // [8,1280,1280]  f32
    float* out = (float*)d_out;                   // e then attention_map

    (void)in_sizes; (void)n_in; (void)out_size;

    dim3 g1(NWCH, HH_N, B);              // 640 blocks
    pool_argmax_kernel<<<g1, 256>>>(label);

    dim3 g2(P / RWARPS, B);              // 1280 blocks
    attn_kernel<<<g2, 256>>>(energy, out);
}

// round 5
// speedup vs baseline: 1.0845x; 1.0845x over previous
#include <cuda_runtime.h>
#include <cstdint>

// Problem constants
constexpr int B  = 8;
constexpr int C  = 19;
constexpr int H  = 320;
constexpr int W  = 2048;
constexpr int HH_OFF = 10;
constexpr int HH_N  = 10;
constexpr int WW   = 128;
constexpr int P    = HH_N * WW;      // 1280
constexpr long long NE = (long long)B * P * P;

constexpr int WCHUNK = 256;
constexpr int NWCH   = W / WCHUNK;   // 8
constexpr int RWARPS = 8;            // rows (=warps) per attn block
constexpr int CH     = P / 4 / 32;   // float4 chunks per lane = 10

__device__ int g_lab[B * P];

// ---------------------------------------------------------------------------
// K1 (fused pool + argmax): unchanged (at ~85% of practical HBM ceiling).
// ---------------------------------------------------------------------------
__global__ __launch_bounds__(256) void pool_argmax_kernel(const float* __restrict__ label)
{
    const int wc = blockIdx.x;
    const int hh = blockIdx.y;
    const int b  = blockIdx.z;
    const int t  = threadIdx.x;
    const int f  = t & 63;
    const int cg = t >> 6;

    __shared__ float ssum[C][17];

    const int h0 = (HH_OFF + hh) * 16;
    const int row_f4 = W / 4;

#pragma unroll
    for (int c4 = 0; c4 < 5; c4++) {
        const int c = c4 * 4 + cg;
        float acc = 0.f;
        if (c < C) {
            const float4* p = reinterpret_cast<const float4*>(
                label + (((size_t)b * C + c) * H + h0) * W + wc * WCHUNK) + f;
#pragma unroll
            for (int r = 0; r < 16; r++) {
                float4 v = __ldcs(p + (size_t)r * row_f4);
                acc += (v.x + v.y) + (v.z + v.w);
            }
        }
        acc += __shfl_xor_sync(0xffffffffu, acc, 1);
        acc += __shfl_xor_sync(0xffffffffu, acc, 2);
        if (c < C && (t & 3) == 0) ssum[c][f >> 2] = acc;
    }
    __syncthreads();

    if (t < 16) {
        float best = ssum[0][t];
        int bi = 0;
#pragma unroll
        for (int c = 1; c < C; c++) {
            float v = ssum[c][t];
            if (v > best) { best = v; bi = c; }
        }
        g_lab[(b * HH_N + hh) * WW + wc * 16 + t] = bi;
    }
}

// ---------------------------------------------------------------------------
// K2 (attn): one warp per row, TWO-PASS to keep register count low.
// Pass 1: energy -> mask-edit -> store ev (regular st, stays in L2) -> exp,
//         accumulate sum. No arrays held.
// Pass 2: read ev back from eout (L2 hit), exp again, store attention_map.
// Warp-shfl reduction only; no __syncthreads in hot path.
// Softmax without max-shift: post-edit values bounded (~|7|), exp safe in f32.
// ---------------------------------------------------------------------------
__global__ __launch_bounds__(256) void attn_kernel(const float* __restrict__ energy,
                                                   float* __restrict__ out)
{
    const int b   = blockIdx.y;
    const int i0  = blockIdx.x * RWARPS;
    const int t   = threadIdx.x;
    const int wid = t >> 5;
    const int lid = t & 31;

    __shared__ int lab_s[P];

    reinterpret_cast<int4*>(lab_s)[t] =
        reinterpret_cast<const int4*>(g_lab + b * P)[t];
    if (t < 64)
        reinterpret_cast<int4*>(lab_s)[256 + t] =
            reinterpret_cast<const int4*>(g_lab + b * P)[256 + t];
    __syncthreads();

    const int i  = i0 + wid;
    const int li = lab_s[i];

    const float4* erow = reinterpret_cast<const float4*>(
        energy + ((size_t)b * P + i) * P);
    float4* eout = reinterpret_cast<float4*>(out + ((size_t)b * P + i) * P);
    float4* aout = reinterpret_cast<float4*>(out + NE + ((size_t)b * P + i) * P);
    const int4* lab4 = reinterpret_cast<const int4*>(lab_s);

    // ---- Pass 1: mask-edit, store e, accumulate exp-sum ----
    float s = 0.f;
#pragma unroll
    for (int k = 0; k < CH; k++) {
        const int j = lid + k * 32;
        float4 en = __ldcs(erow + j);
        int4  lj = lab4[j];

        float4 ev;
        ev.x = (lj.x == li) ? (en.x < 0.f ? 0.5f : en.x) : (en.x > 0.f ? -0.5f : en.x);
        ev.y = (lj.y == li) ? (en.y < 0.f ? 0.5f : en.y) : (en.y > 0.f ? -0.5f : en.y);
        ev.z = (lj.z == li) ? (en.z < 0.f ? 0.5f : en.z) : (en.z > 0.f ? -0.5f : en.z);
        ev.w = (lj.w == li) ? (en.w < 0.f ? 0.5f : en.w) : (en.w > 0.f ? -0.5f : en.w);

        eout[j] = ev;   // regular store: stays L2-resident for pass 2

        s += (__expf(ev.x) + __expf(ev.y)) + (__expf(ev.z) + __expf(ev.w));
    }

#pragma unroll
    for (int o = 16; o > 0; o >>= 1) s += __shfl_xor_sync(0xffffffffu, s, o);
    const float inv = 1.f / s;

    // ---- Pass 2: reload ev from L2, recompute exp, store attention_map ----
#pragma unroll
    for (int k = 0; k < CH; k++) {
        const int j = lid + k * 32;
        float4 ev = eout[j];   // same-thread read-after-write; L2 hit
        float4 am;
        am.x = __expf(ev.x) * inv;
        am.y = __expf(ev.y) * inv;
        am.z = __expf(ev.z) * inv;
        am.w = __expf(ev.w) * inv;
        __stcs(aout + j, am);
    }
}

extern "C" void kernel_launch(void* const* d_in, const int* in_sizes, int n_in,
                              void* d_out, int out_size)
{
    const float* label  = (const float*)d_in[0];  // [8,19,320,2048] f32
    const float* energy = (const float*)d_in[1];  // [8,1280,1280]  f32
    float* out = (float*)d_out;                   // e then attention_map

    (void)in_sizes; (void)n_in; (void)out_size;

    dim3 g1(NWCH, HH_N, B);              // 640 blocks
    pool_argmax_kernel<<<g1, 256>>>(label);

    dim3 g2(P / RWARPS, B);              // 1280 blocks
    attn_kernel<<<g2, 256>>>(energy, out);
}

// round 6
// speedup vs baseline: 1.0967x; 1.0112x over previous
#include <cuda_runtime.h>
#include <cstdint>

// Problem constants
constexpr int B  = 8;
constexpr int C  = 19;
constexpr int H  = 320;
constexpr int W  = 2048;
constexpr int HH_OFF = 10;
constexpr int HH_N  = 10;
constexpr int WW   = 128;
constexpr int P    = HH_N * WW;      // 1280
constexpr long long NE = (long long)B * P * P;

constexpr int WCHUNK = 256;
constexpr int NWCH   = W / WCHUNK;       // 8
constexpr int POOL_PER_B = HH_N * NWCH;  // 80 pool blocks per batch
constexpr int POOL_BLOCKS = B * POOL_PER_B;   // 640
constexpr int RWARPS = 8;                // rows per attn block
constexpr int ATTN_PER_B = P / RWARPS;   // 160
constexpr int ATTN_BLOCKS = B * ATTN_PER_B;   // 1280
constexpr int CH = P / 4 / 32;           // float4 chunks per lane = 10

__device__ int g_lab[B * P];
__device__ int g_done[B];   // pool blocks completed per batch (memset to 0 each launch)

// ---------------------------------------------------------------------------
// Fused kernel. Blocks [0,640): pool+argmax, batch-major. Blocks [640,1920):
// attn, batch-major; each spins until its batch's 80 pool blocks are done.
// All pool blocks fit in scheduling wave 1 (1184 resident CTAs) -> no deadlock.
// ---------------------------------------------------------------------------
__global__ __launch_bounds__(256) void fused_kernel(const float* __restrict__ label,
                                                    const float* __restrict__ energy,
                                                    float* __restrict__ out)
{
    const int bid = blockIdx.x;
    const int t   = threadIdx.x;

    __shared__ int lab_s[P];   // attn path (5 KB); pool path reuses front as ssum

    if (bid < POOL_BLOCKS) {
        // ================= POOL + ARGMAX =================
        const int b   = bid / POOL_PER_B;
        const int rem = bid % POOL_PER_B;
        const int hh  = rem / NWCH;
        const int wc  = rem % NWCH;
        const int f   = t & 63;
        const int cg  = t >> 6;

        float (*ssum)[17] = reinterpret_cast<float(*)[17]>(lab_s); // 19*17*4 = 1.3KB

        const int h0 = (HH_OFF + hh) * 16;
        const int row_f4 = W / 4;

#pragma unroll
        for (int c4 = 0; c4 < 5; c4++) {
            const int c = c4 * 4 + cg;
            float acc = 0.f;
            if (c < C) {
                const float4* p = reinterpret_cast<const float4*>(
                    label + (((size_t)b * C + c) * H + h0) * W + wc * WCHUNK) + f;
#pragma unroll
                for (int r = 0; r < 16; r++) {
                    float4 v = __ldcs(p + (size_t)r * row_f4);
                    acc += (v.x + v.y) + (v.z + v.w);
                }
            }
            acc += __shfl_xor_sync(0xffffffffu, acc, 1);
            acc += __shfl_xor_sync(0xffffffffu, acc, 2);
            if (c < C && (t & 3) == 0) ssum[c][f >> 2] = acc;
        }
        __syncthreads();

        if (t < 16) {
            float best = ssum[0][t];
            int bi = 0;
#pragma unroll
            for (int c = 1; c < C; c++) {
                float v = ssum[c][t];
                if (v > best) { best = v; bi = c; }   // strict '>' = first-max
            }
            g_lab[(b * HH_N + hh) * WW + wc * 16 + t] = bi;
        }
        __syncthreads();
        __threadfence();
        if (t == 0) atomicAdd(&g_done[b], 1);
    } else {
        // ================= ATTN (two-pass, warp-per-row) =================
        const int aid = bid - POOL_BLOCKS;
        const int b   = aid / ATTN_PER_B;
        const int i0  = (aid % ATTN_PER_B) * RWARPS;
        const int wid = t >> 5;
        const int lid = t & 31;

        // Wait for this batch's labels
        if (t == 0) {
            while (atomicAdd(&g_done[b], 0) < POOL_PER_B) __nanosleep(200);
        }
        __syncthreads();
        __threadfence();

        reinterpret_cast<int4*>(lab_s)[t] =
            reinterpret_cast<const int4*>(g_lab + b * P)[t];
        if (t < 64)
            reinterpret_cast<int4*>(lab_s)[256 + t] =
                reinterpret_cast<const int4*>(g_lab + b * P)[256 + t];
        __syncthreads();

        const int i  = i0 + wid;
        const int li = lab_s[i];

        const float4* erow = reinterpret_cast<const float4*>(
            energy + ((size_t)b * P + i) * P);
        float4* eout = reinterpret_cast<float4*>(out + ((size_t)b * P + i) * P);
        float4* aout = reinterpret_cast<float4*>(out + NE + ((size_t)b * P + i) * P);
        const int4* lab4 = reinterpret_cast<const int4*>(lab_s);

        // Pass 1: mask-edit, store e (L2-resident), accumulate exp-sum.
        // No max-shift: post-edit values bounded (~|7|), f32 exp safe,
        // softmax shift-invariant.
        float s = 0.f;
#pragma unroll
        for (int k = 0; k < CH; k++) {
            const int j = lid + k * 32;
            float4 en = __ldcs(erow + j);
            int4  lj = lab4[j];

            float4 ev;
            ev.x = (lj.x == li) ? (en.x < 0.f ? 0.5f : en.x) : (en.x > 0.f ? -0.5f : en.x);
            ev.y = (lj.y == li) ? (en.y < 0.f ? 0.5f : en.y) : (en.y > 0.f ? -0.5f : en.y);
            ev.z = (lj.z == li) ? (en.z < 0.f ? 0.5f : en.z) : (en.z > 0.f ? -0.5f : en.z);
            ev.w = (lj.w == li) ? (en.w < 0.f ? 0.5f : en.w) : (en.w > 0.f ? -0.5f : en.w);

            eout[j] = ev;

            s += (__expf(ev.x) + __expf(ev.y)) + (__expf(ev.z) + __expf(ev.w));
        }

#pragma unroll
        for (int o = 16; o > 0; o >>= 1) s += __shfl_xor_sync(0xffffffffu, s, o);
        const float inv = 1.f / s;

        // Pass 2: reload ev from L2, recompute exp, store attention_map.
#pragma unroll
        for (int k = 0; k < CH; k++) {
            const int j = lid + k * 32;
            float4 ev = eout[j];
            float4 am;
            am.x = __expf(ev.x) * inv;
            am.y = __expf(ev.y) * inv;
            am.z = __expf(ev.z) * inv;
            am.w = __expf(ev.w) * inv;
            __stcs(aout + j, am);
        }
    }
}

extern "C" void kernel_launch(void* const* d_in, const int* in_sizes, int n_in,
                              void* d_out, int out_size)
{
    const float* label  = (const float*)d_in[0];  // [8,19,320,2048] f32
    const float* energy = (const float*)d_in[1];  // [8,1280,1280]  f32
    float* out = (float*)d_out;                   // e then attention_map

    (void)in_sizes; (void)n_in; (void)out_size;

    void* done_addr = nullptr;
    cudaGetSymbolAddress(&done_addr, g_done);
    cudaMemsetAsync(done_addr, 0, B * sizeof(int));

    fused_kernel<<<POOL_BLOCKS + ATTN_BLOCKS, 256>>>(label, energy, out);
}